// round 1
// baseline (speedup 1.0000x reference)
#include <cuda_runtime.h>

// Problem constants (fixed by the dataset)
#define NB    128          // graphs (B)
#define NN    256          // nodes per graph
#define DPE   16           // D_pe / eigen dim
#define MM    4            // M psi copies
#define HPSI  32
#define HP    16
#define HG    64
#define NSUM  (NB*NN)      // 32768
#define EDGES (NSUM*16)    // 524288
#define EPG   (EDGES/NB)   // 4096 edges per graph (edges are graph-contiguous)
#define VPAD  20           // padded row stride (floats) -> conflict-free LDS.128

// Scratch (device globals: no allocation allowed)
__device__ float g_Z[NB*DPE*MM];     // masked Z[b][d][m]
__device__ float g_x[NSUM*HP];       // pooled features x[node][h]

// ---------------------------------------------------------------------------
// Kernel A: per-graph eigenvalue-count mask + psi MLP -> Z[b,d,m]
// ---------------------------------------------------------------------------
__global__ void kernelA(const float* __restrict__ Lambda,
                        const float* __restrict__ pW1, const float* __restrict__ pb1,
                        const float* __restrict__ pW2, const float* __restrict__ pb2,
                        const int*   __restrict__ batch)
{
    int b = blockIdx.x;
    int t = threadIdx.x;
    __shared__ int s_cnt;
    if (t == 0) s_cnt = 0;
    __syncthreads();
    int local = 0;
    for (int i = t; i < NSUM; i += blockDim.x) local += (batch[i] == b);
    #pragma unroll
    for (int off = 16; off; off >>= 1) local += __shfl_down_sync(0xffffffffu, local, off);
    if ((t & 31) == 0) atomicAdd(&s_cnt, local);
    __syncthreads();
    int cnt = s_cnt;

    if (t < DPE*MM) {
        int d = t >> 2, m = t & 3;
        float lam = Lambda[b*DPE + d];
        float acc = pb2[m];
        #pragma unroll
        for (int h = 0; h < HPSI; h++) {
            float v = fmaf(lam, pW1[m*HPSI + h], pb1[m*HPSI + h]);
            acc = fmaf(fmaxf(v, 0.f), pW2[m*HPSI + h], acc);
        }
        if (d >= cnt) acc = 0.f;
        g_Z[(b*DPE + d)*MM + m] = acc;
    }
}

// ---------------------------------------------------------------------------
// Kernel B: pairwise phase, symmetric-halved.
//   For each unordered pair {n,k} in a graph:
//     w_m = sum_d V[n,d]*Z[d,m]*V[k,d]  (symmetric in n,k)
//     r_h = relu(sum_m w_m * Wp1[m,h] + bp1[h])
//     x[n] += r ; x[k] += r   (diagonal counted once)
//   Schedule: thread n handles offset-o pair (n, n+o mod 256), o = 0..128;
//   result vectors exchanged via shared memory so each pair is computed once.
// ---------------------------------------------------------------------------
#define COMPUTE_R(kk, rr) do {                                                  \
    const float* vrow_ = &Vs[(kk)*VPAD];                                        \
    float4 q0_ = *(const float4*)(vrow_);                                       \
    float4 q1_ = *(const float4*)(vrow_ + 4);                                   \
    float4 q2_ = *(const float4*)(vrow_ + 8);                                   \
    float4 q3_ = *(const float4*)(vrow_ + 12);                                  \
    float vk_[16] = {q0_.x,q0_.y,q0_.z,q0_.w, q1_.x,q1_.y,q1_.z,q1_.w,          \
                     q2_.x,q2_.y,q2_.z,q2_.w, q3_.x,q3_.y,q3_.z,q3_.w};         \
    float w_[4];                                                                \
    _Pragma("unroll")                                                           \
    for (int m_ = 0; m_ < 4; m_++) {                                            \
        float s0_ = An[m_][0]*vk_[0];                                           \
        float s1_ = An[m_][1]*vk_[1];                                           \
        _Pragma("unroll")                                                       \
        for (int d_ = 2; d_ < 16; d_ += 2) {                                    \
            s0_ = fmaf(An[m_][d_],   vk_[d_],   s0_);                           \
            s1_ = fmaf(An[m_][d_+1], vk_[d_+1], s1_);                           \
        }                                                                       \
        w_[m_] = s0_ + s1_;                                                     \
    }                                                                           \
    _Pragma("unroll")                                                           \
    for (int h_ = 0; h_ < 16; h_++) {                                           \
        float p_ = fmaf(w_[0], wp[0][h_], bps[h_]);                             \
        p_ = fmaf(w_[1], wp[1][h_], p_);                                        \
        p_ = fmaf(w_[2], wp[2][h_], p_);                                        \
        p_ = fmaf(w_[3], wp[3][h_], p_);                                        \
        rr[h_] = fmaxf(p_, 0.f);                                                \
    }                                                                           \
} while (0)

__global__ void __launch_bounds__(256, 1) kernelB(const float* __restrict__ V,
                                                  const float* __restrict__ Wp1,
                                                  const float* __restrict__ bp1)
{
    __shared__ float Vs [NN*VPAD];   // 20 KB, padded (stride 20) for LDS.128
    __shared__ float xch[NN*VPAD];   // 20 KB exchange buffer
    __shared__ float zs [DPE*MM];

    int b = blockIdx.x;
    int n = threadIdx.x;

    // Load V tile [256 x 16] into padded smem
    const float4* vg = (const float4*)(V + (size_t)b*NN*DPE);
    for (int i = n; i < NN*DPE/4; i += 256) {
        float4 v = vg[i];
        *(float4*)&Vs[(i >> 2)*VPAD + ((i & 3) << 2)] = v;
    }
    if (n < DPE*MM) zs[n] = g_Z[b*DPE*MM + n];

    // Weights in registers (shared by every pair this thread computes)
    float wp[MM][HP];
    float bps[HP];
    #pragma unroll
    for (int m = 0; m < MM; m++)
        #pragma unroll
        for (int h = 0; h < HP; h++) wp[m][h] = Wp1[m*HP + h];
    #pragma unroll
    for (int h = 0; h < HP; h++) bps[h] = bp1[h];
    __syncthreads();

    // Per-thread scaled row: An[m][d] = V[n,d] * Z[d,m]
    float An[MM][DPE];
    #pragma unroll
    for (int d = 0; d < DPE; d++) {
        float vd = Vs[n*VPAD + d];
        #pragma unroll
        for (int m = 0; m < MM; m++) An[m][d] = vd * zs[d*MM + m];
    }

    float acc[HP];
    #pragma unroll
    for (int h = 0; h < HP; h++) acc[h] = 0.f;

    // o = 0: diagonal pair (n,n) counted once
    {
        float r[HP];
        COMPUTE_R(n, r);
        #pragma unroll
        for (int h = 0; h < HP; h++) acc[h] += r[h];
    }

    // o = 1..128: each unordered pair computed exactly once; exchange via smem
    for (int o = 1; o <= 128; o++) {
        int  k   = (n + o) & 255;
        bool act = (o < 128) || (n < 128);   // o=128: only lower half computes
        float r[HP];
        if (act) {
            COMPUTE_R(k, r);
            #pragma unroll
            for (int h = 0; h < HP; h++) acc[h] += r[h];
        }
        __syncthreads();   // previous step's exchange reads finished
        if (act) {
            *(float4*)&xch[n*VPAD +  0] = make_float4(r[0],  r[1],  r[2],  r[3]);
            *(float4*)&xch[n*VPAD +  4] = make_float4(r[4],  r[5],  r[6],  r[7]);
            *(float4*)&xch[n*VPAD +  8] = make_float4(r[8],  r[9],  r[10], r[11]);
            *(float4*)&xch[n*VPAD + 12] = make_float4(r[12], r[13], r[14], r[15]);
        }
        __syncthreads();   // writes visible
        if (o < 128 || n >= 128) {
            int j = (n - o) & 255;       // partner that computed pair (j, n)
            float4 a0 = *(const float4*)&xch[j*VPAD +  0];
            float4 a1 = *(const float4*)&xch[j*VPAD +  4];
            float4 a2 = *(const float4*)&xch[j*VPAD +  8];
            float4 a3 = *(const float4*)&xch[j*VPAD + 12];
            acc[0]+=a0.x; acc[1]+=a0.y; acc[2]+=a0.z; acc[3]+=a0.w;
            acc[4]+=a1.x; acc[5]+=a1.y; acc[6]+=a1.z; acc[7]+=a1.w;
            acc[8]+=a2.x; acc[9]+=a2.y; acc[10]+=a2.z; acc[11]+=a2.w;
            acc[12]+=a3.x; acc[13]+=a3.y; acc[14]+=a3.z; acc[15]+=a3.w;
        }
    }

    float* xo = g_x + (size_t)(b*NN + n)*HP;
    *(float4*)&xo[0]  = make_float4(acc[0],  acc[1],  acc[2],  acc[3]);
    *(float4*)&xo[4]  = make_float4(acc[4],  acc[5],  acc[6],  acc[7]);
    *(float4*)&xo[8]  = make_float4(acc[8],  acc[9],  acc[10], acc[11]);
    *(float4*)&xo[12] = make_float4(acc[12], acc[13], acc[14], acc[15]);
}

// ---------------------------------------------------------------------------
// Kernel C: per-graph GIN aggregation (CSR counting-sort in smem, no atomics
// in the gather) fused with the 16->64->16 output MLP.
// ---------------------------------------------------------------------------
__global__ void kernelC(const float* __restrict__ Wg1, const float* __restrict__ bg1,
                        const float* __restrict__ Wg2, const float* __restrict__ bg2,
                        const float* __restrict__ eps, const int* __restrict__ edge_index,
                        float* __restrict__ out)
{
    __shared__ float xs[NN*VPAD];        // 20480 B
    __shared__ int   sorted_src[EPG];    // 16384 B
    __shared__ float Wg1s[HP*HG];        //  4096 B
    __shared__ float Wg2s[HG*DPE];       //  4096 B
    __shared__ float bg1s[HG];
    __shared__ float bg2s[DPE];
    __shared__ int   cnt[NN];            // histogram, then scatter cursor
    __shared__ int   sc[NN];             // scan workspace
    __shared__ int   start[NN+1];

    int b = blockIdx.x, t = threadIdx.x;
    int base = b*NN;

    // Stage x tile + weights
    const float4* xg = (const float4*)(g_x + (size_t)b*NN*HP);
    for (int i = t; i < NN*HP/4; i += 256) {
        float4 v = xg[i];
        *(float4*)&xs[(i >> 2)*VPAD + ((i & 3) << 2)] = v;
    }
    for (int i = t; i < HP*HG;  i += 256) Wg1s[i] = Wg1[i];
    for (int i = t; i < HG*DPE; i += 256) Wg2s[i] = Wg2[i];
    if (t < HG)  bg1s[t] = bg1[t];
    if (t < DPE) bg2s[t] = bg2[t];
    cnt[t] = 0;
    __syncthreads();

    const int* srcp = edge_index + (size_t)b*EPG;
    const int* dstp = edge_index + (size_t)EDGES + (size_t)b*EPG;

    // Histogram of destinations
    for (int e = t; e < EPG; e += 256) {
        int d = dstp[e] - base;
        atomicAdd(&cnt[d], 1);
    }
    __syncthreads();

    // Hillis-Steele inclusive scan -> exclusive offsets
    sc[t] = cnt[t];
    __syncthreads();
    for (int off = 1; off < NN; off <<= 1) {
        int add = (t >= off) ? sc[t - off] : 0;
        __syncthreads();
        sc[t] += add;
        __syncthreads();
    }
    start[t + 1] = sc[t];
    if (t == 0) start[0] = 0;
    __syncthreads();
    cnt[t] = start[t];   // cursor
    __syncthreads();

    // Scatter: sort src by dst
    for (int e = t; e < EPG; e += 256) {
        int d = dstp[e] - base;
        int pos = atomicAdd(&cnt[d], 1);
        sorted_src[pos] = srcp[e] - base;
    }
    __syncthreads();

    // Gather (atomic-free) for node n = t
    float agg[HP];
    #pragma unroll
    for (int h = 0; h < HP; h++) agg[h] = 0.f;
    int s0 = start[t], s1 = start[t + 1];
    for (int idx = s0; idx < s1; idx++) {
        int s = sorted_src[idx];
        const float* xr = &xs[s*VPAD];
        float4 a0 = *(const float4*)&xr[0];
        float4 a1 = *(const float4*)&xr[4];
        float4 a2 = *(const float4*)&xr[8];
        float4 a3 = *(const float4*)&xr[12];
        agg[0]+=a0.x; agg[1]+=a0.y; agg[2]+=a0.z; agg[3]+=a0.w;
        agg[4]+=a1.x; agg[5]+=a1.y; agg[6]+=a1.z; agg[7]+=a1.w;
        agg[8]+=a2.x; agg[9]+=a2.y; agg[10]+=a2.z; agg[11]+=a2.w;
        agg[12]+=a3.x; agg[13]+=a3.y; agg[14]+=a3.z; agg[15]+=a3.w;
    }

    // y = (1+eps)*x + agg ; h2 = relu(y@Wg1 + bg1) ; out = h2@Wg2 + bg2
    float ge = 1.f + eps[0];
    float y[HP];
    #pragma unroll
    for (int h = 0; h < HP; h++) y[h] = fmaf(ge, xs[t*VPAD + h], agg[h]);

    float tg[HG];
    #pragma unroll
    for (int j = 0; j < HG; j++) tg[j] = bg1s[j];
    #pragma unroll
    for (int h = 0; h < HP; h++) {
        float yh = y[h];
        #pragma unroll
        for (int j = 0; j < HG; j += 4) {
            float4 wv = *(const float4*)&Wg1s[h*HG + j];
            tg[j+0] = fmaf(yh, wv.x, tg[j+0]);
            tg[j+1] = fmaf(yh, wv.y, tg[j+1]);
            tg[j+2] = fmaf(yh, wv.z, tg[j+2]);
            tg[j+3] = fmaf(yh, wv.w, tg[j+3]);
        }
    }
    #pragma unroll
    for (int j = 0; j < HG; j++) tg[j] = fmaxf(tg[j], 0.f);

    float o2[DPE];
    #pragma unroll
    for (int d = 0; d < DPE; d++) o2[d] = bg2s[d];
    #pragma unroll
    for (int j = 0; j < HG; j++) {
        float tj = tg[j];
        #pragma unroll
        for (int d = 0; d < DPE; d += 4) {
            float4 wv = *(const float4*)&Wg2s[j*DPE + d];
            o2[d+0] = fmaf(tj, wv.x, o2[d+0]);
            o2[d+1] = fmaf(tj, wv.y, o2[d+1]);
            o2[d+2] = fmaf(tj, wv.z, o2[d+2]);
            o2[d+3] = fmaf(tj, wv.w, o2[d+3]);
        }
    }

    float* op = out + (size_t)(base + t)*DPE;
    *(float4*)&op[0]  = make_float4(o2[0],  o2[1],  o2[2],  o2[3]);
    *(float4*)&op[4]  = make_float4(o2[4],  o2[5],  o2[6],  o2[7]);
    *(float4*)&op[8]  = make_float4(o2[8],  o2[9],  o2[10], o2[11]);
    *(float4*)&op[12] = make_float4(o2[12], o2[13], o2[14], o2[15]);
}

// ---------------------------------------------------------------------------
extern "C" void kernel_launch(void* const* d_in, const int* in_sizes, int n_in,
                              void* d_out, int out_size)
{
    const float* Lambda = (const float*)d_in[0];
    const float* V      = (const float*)d_in[1];
    const float* pW1    = (const float*)d_in[2];
    const float* pb1    = (const float*)d_in[3];
    const float* pW2    = (const float*)d_in[4];
    const float* pb2    = (const float*)d_in[5];
    const float* Wp1    = (const float*)d_in[6];
    const float* bp1    = (const float*)d_in[7];
    const float* Wg1    = (const float*)d_in[8];
    const float* bg1    = (const float*)d_in[9];
    const float* Wg2    = (const float*)d_in[10];
    const float* bg2    = (const float*)d_in[11];
    const float* eps    = (const float*)d_in[12];
    const int*   edge_index = (const int*)d_in[13];
    const int*   batch  = (const int*)d_in[14];
    float* out = (float*)d_out;

    kernelA<<<NB, 128>>>(Lambda, pW1, pb1, pW2, pb2, batch);
    kernelB<<<NB, 256>>>(V, Wp1, bp1);
    kernelC<<<NB, 256>>>(Wg1, bg1, Wg2, bg2, eps, edge_index, out);
}

// round 2
// speedup vs baseline: 1.1870x; 1.1870x over previous
#include <cuda_runtime.h>

// Problem constants (fixed by the dataset)
#define NB    128          // graphs (B)
#define NN    256          // nodes per graph
#define DPE   16           // D_pe / eigen dim
#define MM    4            // M psi copies
#define HPSI  32
#define HP    16
#define HG    64
#define NSUM  (NB*NN)      // 32768
#define EDGES (NSUM*16)    // 524288
#define EPG   (EDGES/NB)   // 4096 edges per graph (edges are graph-contiguous)
#define VPAD  20           // padded row stride (floats) -> conflict-free LDS.128

typedef unsigned long long u64;

// Scratch (device globals: no allocation allowed)
__device__ float g_x[NSUM*HP];       // pooled features x[node][h]

// ---------------- packed f32x2 helpers ----------------
__device__ __forceinline__ u64 pk2(float lo, float hi) {
    u64 r; asm("mov.b64 %0,{%1,%2};" : "=l"(r) : "f"(lo), "f"(hi)); return r;
}
__device__ __forceinline__ void upk2(u64 v, float& lo, float& hi) {
    asm("mov.b64 {%0,%1},%2;" : "=f"(lo), "=f"(hi) : "l"(v));
}
__device__ __forceinline__ u64 fma2(u64 a, u64 b, u64 c) {
    u64 d; asm("fma.rn.f32x2 %0,%1,%2,%3;" : "=l"(d) : "l"(a), "l"(b), "l"(c)); return d;
}
__device__ __forceinline__ u64 mul2(u64 a, u64 b) {
    u64 d; asm("mul.rn.f32x2 %0,%1,%2;" : "=l"(d) : "l"(a), "l"(b)); return d;
}

// ---------------------------------------------------------------------------
// Kernel B (fused): psi MLP + mask (binary-search count) + pairwise phase.
//   For each unordered pair {n,k} in a graph:
//     w_m = sum_d V[n,d]*Z[d,m]*V[k,d]  (symmetric in n,k)
//     r_h = relu(sum_m w_m * Wp1[m,h] + bp1[h])
//     x[n] += r ; x[k] += r   (diagonal counted once)
//   Thread n handles offset-o pair (n, n+o mod 256), o = 0..128; the result
//   is exchanged through double-buffered shared memory (1 barrier / step).
// ---------------------------------------------------------------------------
#define COMPUTE_R2(kk, rr) do {                                                 \
    const ulonglong2* vr_ = (const ulonglong2*)&Vs[(kk)*VPAD];                  \
    ulonglong2 a_ = vr_[0], b_ = vr_[1], c_ = vr_[2], d_ = vr_[3];              \
    u64 vk_[8] = {a_.x, a_.y, b_.x, b_.y, c_.x, c_.y, d_.x, d_.y};              \
    float w_[4];                                                                \
    _Pragma("unroll")                                                           \
    for (int m_ = 0; m_ < 4; m_++) {                                            \
        u64 s_ = mul2(An2[m_][0], vk_[0]);                                      \
        _Pragma("unroll")                                                       \
        for (int j_ = 1; j_ < 8; j_++) s_ = fma2(An2[m_][j_], vk_[j_], s_);     \
        float lo_, hi_; upk2(s_, lo_, hi_);                                     \
        w_[m_] = lo_ + hi_;                                                     \
    }                                                                           \
    u64 wm2_[4];                                                                \
    _Pragma("unroll")                                                           \
    for (int m_ = 0; m_ < 4; m_++) wm2_[m_] = pk2(w_[m_], w_[m_]);              \
    _Pragma("unroll")                                                           \
    for (int hp_ = 0; hp_ < 8; hp_++) {                                         \
        u64 p_ = fma2(wm2_[0], wp2[0][hp_], bps2[hp_]);                         \
        p_ = fma2(wm2_[1], wp2[1][hp_], p_);                                    \
        p_ = fma2(wm2_[2], wp2[2][hp_], p_);                                    \
        p_ = fma2(wm2_[3], wp2[3][hp_], p_);                                    \
        float lo_, hi_; upk2(p_, lo_, hi_);                                     \
        rr[2*hp_]   = fmaxf(lo_, 0.f);                                          \
        rr[2*hp_+1] = fmaxf(hi_, 0.f);                                          \
    }                                                                           \
} while (0)

__global__ void __launch_bounds__(256, 1) kernelB(
        const float* __restrict__ V,
        const float* __restrict__ Lambda,
        const float* __restrict__ pW1, const float* __restrict__ pb1,
        const float* __restrict__ pW2, const float* __restrict__ pb2,
        const float* __restrict__ Wp1, const float* __restrict__ bp1,
        const int*   __restrict__ batch)
{
    extern __shared__ float sm[];
    float* Vs   = sm;                    // NN*VPAD = 5120 floats
    float* xch0 = sm + NN*VPAD;          // 5120
    float* xch1 = sm + 2*NN*VPAD;        // 5120
    float* zs   = sm + 3*NN*VPAD;        // 64
    __shared__ int bnds[2];

    int b = blockIdx.x;
    int n = threadIdx.x;

    // Load V tile [256 x 16] into padded smem
    const float4* vg = (const float4*)(V + (size_t)b*NN*DPE);
    for (int i = n; i < NN*DPE/4; i += 256) {
        float4 v = vg[i];
        *(float4*)&Vs[(i >> 2)*VPAD + ((i & 3) << 2)] = v;
    }

    // psi MLP (threads 0..63), eigen-count via binary search (threads 0,1)
    float pacc = 0.f;
    if (n < DPE*MM) {
        int d = n >> 2, m = n & 3;
        float lam = Lambda[b*DPE + d];
        pacc = pb2[m];
        #pragma unroll
        for (int h = 0; h < HPSI; h++) {
            float v = fmaf(lam, pW1[m*HPSI + h], pb1[m*HPSI + h]);
            pacc = fmaf(fmaxf(v, 0.f), pW2[m*HPSI + h], pacc);
        }
    }
    if (n < 2) {
        int key = b + n;            // first index with batch[i] >= key
        int lo = 0, hi = NSUM;
        while (lo < hi) {
            int mid = (lo + hi) >> 1;
            if (batch[mid] < key) lo = mid + 1; else hi = mid;
        }
        bnds[n] = lo;
    }

    // Projection weights, packed, in registers
    u64 wp2[MM][HP/2];
    u64 bps2[HP/2];
    #pragma unroll
    for (int m = 0; m < MM; m++)
        #pragma unroll
        for (int hp = 0; hp < HP/2; hp++)
            wp2[m][hp] = pk2(Wp1[m*HP + 2*hp], Wp1[m*HP + 2*hp + 1]);
    #pragma unroll
    for (int hp = 0; hp < HP/2; hp++) bps2[hp] = pk2(bp1[2*hp], bp1[2*hp+1]);

    __syncthreads();
    if (n < DPE*MM) {
        int cnt = bnds[1] - bnds[0];
        zs[n] = ((n >> 2) < cnt) ? pacc : 0.f;
    }
    __syncthreads();

    // Per-thread scaled row (packed over d): An2[m][j] holds
    //   (V[n,2j]*Z[2j,m] , V[n,2j+1]*Z[2j+1,m])
    float vn[DPE];
    {
        const float4* vrow = (const float4*)&Vs[n*VPAD];
        float4 q0 = vrow[0], q1 = vrow[1], q2 = vrow[2], q3 = vrow[3];
        vn[0]=q0.x; vn[1]=q0.y; vn[2]=q0.z; vn[3]=q0.w;
        vn[4]=q1.x; vn[5]=q1.y; vn[6]=q1.z; vn[7]=q1.w;
        vn[8]=q2.x; vn[9]=q2.y; vn[10]=q2.z; vn[11]=q2.w;
        vn[12]=q3.x; vn[13]=q3.y; vn[14]=q3.z; vn[15]=q3.w;
    }
    u64 An2[MM][DPE/2];
    #pragma unroll
    for (int j = 0; j < DPE/2; j++) {
        #pragma unroll
        for (int m = 0; m < MM; m++)
            An2[m][j] = pk2(vn[2*j] * zs[(2*j)*MM + m],
                            vn[2*j+1] * zs[(2*j+1)*MM + m]);
    }

    float acc[HP];
    #pragma unroll
    for (int h = 0; h < HP; h++) acc[h] = 0.f;

    // o = 0: diagonal pair (n,n) counted once
    {
        float r[HP];
        COMPUTE_R2(n, r);
        #pragma unroll
        for (int h = 0; h < HP; h++) acc[h] += r[h];
    }

    // o = 1..128: each unordered pair computed exactly once
    for (int o = 1; o <= 128; o++) {
        int  k   = (n + o) & 255;
        bool act = (o < 128) || (n < 128);   // o=128: only lower half computes
        float* xch = (o & 1) ? xch1 : xch0;
        float r[HP];
        if (act) {
            COMPUTE_R2(k, r);
            #pragma unroll
            for (int h = 0; h < HP; h++) acc[h] += r[h];
            *(float4*)&xch[n*VPAD +  0] = make_float4(r[0],  r[1],  r[2],  r[3]);
            *(float4*)&xch[n*VPAD +  4] = make_float4(r[4],  r[5],  r[6],  r[7]);
            *(float4*)&xch[n*VPAD +  8] = make_float4(r[8],  r[9],  r[10], r[11]);
            *(float4*)&xch[n*VPAD + 12] = make_float4(r[12], r[13], r[14], r[15]);
        }
        __syncthreads();   // writes of buffer (o&1) visible; prior reads done
        if (o < 128 || n >= 128) {
            int j = (n - o) & 255;       // partner that computed pair (j, n)
            float4 a0 = *(const float4*)&xch[j*VPAD +  0];
            float4 a1 = *(const float4*)&xch[j*VPAD +  4];
            float4 a2 = *(const float4*)&xch[j*VPAD +  8];
            float4 a3 = *(const float4*)&xch[j*VPAD + 12];
            acc[0]+=a0.x; acc[1]+=a0.y; acc[2]+=a0.z; acc[3]+=a0.w;
            acc[4]+=a1.x; acc[5]+=a1.y; acc[6]+=a1.z; acc[7]+=a1.w;
            acc[8]+=a2.x; acc[9]+=a2.y; acc[10]+=a2.z; acc[11]+=a2.w;
            acc[12]+=a3.x; acc[13]+=a3.y; acc[14]+=a3.z; acc[15]+=a3.w;
        }
    }

    float* xo = g_x + (size_t)(b*NN + n)*HP;
    *(float4*)&xo[0]  = make_float4(acc[0],  acc[1],  acc[2],  acc[3]);
    *(float4*)&xo[4]  = make_float4(acc[4],  acc[5],  acc[6],  acc[7]);
    *(float4*)&xo[8]  = make_float4(acc[8],  acc[9],  acc[10], acc[11]);
    *(float4*)&xo[12] = make_float4(acc[12], acc[13], acc[14], acc[15]);
}

// ---------------------------------------------------------------------------
// Kernel C: per-graph GIN aggregation (CSR counting-sort in smem, no atomics
// in the gather) fused with the 16->64->16 output MLP.
// ---------------------------------------------------------------------------
__global__ void kernelC(const float* __restrict__ Wg1, const float* __restrict__ bg1,
                        const float* __restrict__ Wg2, const float* __restrict__ bg2,
                        const float* __restrict__ eps, const int* __restrict__ edge_index,
                        float* __restrict__ out)
{
    __shared__ float xs[NN*VPAD];        // 20480 B
    __shared__ int   sorted_src[EPG];    // 16384 B
    __shared__ float Wg1s[HP*HG];        //  4096 B
    __shared__ float Wg2s[HG*DPE];       //  4096 B
    __shared__ float bg1s[HG];
    __shared__ float bg2s[DPE];
    __shared__ int   cnt[NN];            // histogram, then scatter cursor
    __shared__ int   sc[NN];             // scan workspace
    __shared__ int   start[NN+1];

    int b = blockIdx.x, t = threadIdx.x;
    int base = b*NN;

    // Stage x tile + weights
    const float4* xg = (const float4*)(g_x + (size_t)b*NN*HP);
    for (int i = t; i < NN*HP/4; i += 256) {
        float4 v = xg[i];
        *(float4*)&xs[(i >> 2)*VPAD + ((i & 3) << 2)] = v;
    }
    for (int i = t; i < HP*HG;  i += 256) Wg1s[i] = Wg1[i];
    for (int i = t; i < HG*DPE; i += 256) Wg2s[i] = Wg2[i];
    if (t < HG)  bg1s[t] = bg1[t];
    if (t < DPE) bg2s[t] = bg2[t];
    cnt[t] = 0;
    __syncthreads();

    const int* srcp = edge_index + (size_t)b*EPG;
    const int* dstp = edge_index + (size_t)EDGES + (size_t)b*EPG;

    // Histogram of destinations
    for (int e = t; e < EPG; e += 256) {
        int d = dstp[e] - base;
        atomicAdd(&cnt[d], 1);
    }
    __syncthreads();

    // Hillis-Steele inclusive scan -> exclusive offsets
    sc[t] = cnt[t];
    __syncthreads();
    for (int off = 1; off < NN; off <<= 1) {
        int add = (t >= off) ? sc[t - off] : 0;
        __syncthreads();
        sc[t] += add;
        __syncthreads();
    }
    start[t + 1] = sc[t];
    if (t == 0) start[0] = 0;
    __syncthreads();
    cnt[t] = start[t];   // cursor
    __syncthreads();

    // Scatter: sort src by dst
    for (int e = t; e < EPG; e += 256) {
        int d = dstp[e] - base;
        int pos = atomicAdd(&cnt[d], 1);
        sorted_src[pos] = srcp[e] - base;
    }
    __syncthreads();

    // Gather (atomic-free) for node n = t
    float agg[HP];
    #pragma unroll
    for (int h = 0; h < HP; h++) agg[h] = 0.f;
    int s0 = start[t], s1 = start[t + 1];
    for (int idx = s0; idx < s1; idx++) {
        int s = sorted_src[idx];
        const float* xr = &xs[s*VPAD];
        float4 a0 = *(const float4*)&xr[0];
        float4 a1 = *(const float4*)&xr[4];
        float4 a2 = *(const float4*)&xr[8];
        float4 a3 = *(const float4*)&xr[12];
        agg[0]+=a0.x; agg[1]+=a0.y; agg[2]+=a0.z; agg[3]+=a0.w;
        agg[4]+=a1.x; agg[5]+=a1.y; agg[6]+=a1.z; agg[7]+=a1.w;
        agg[8]+=a2.x; agg[9]+=a2.y; agg[10]+=a2.z; agg[11]+=a2.w;
        agg[12]+=a3.x; agg[13]+=a3.y; agg[14]+=a3.z; agg[15]+=a3.w;
    }

    // y = (1+eps)*x + agg ; h2 = relu(y@Wg1 + bg1) ; out = h2@Wg2 + bg2
    float ge = 1.f + eps[0];
    float y[HP];
    #pragma unroll
    for (int h = 0; h < HP; h++) y[h] = fmaf(ge, xs[t*VPAD + h], agg[h]);

    float tg[HG];
    #pragma unroll
    for (int j = 0; j < HG; j++) tg[j] = bg1s[j];
    #pragma unroll
    for (int h = 0; h < HP; h++) {
        float yh = y[h];
        #pragma unroll
        for (int j = 0; j < HG; j += 4) {
            float4 wv = *(const float4*)&Wg1s[h*HG + j];
            tg[j+0] = fmaf(yh, wv.x, tg[j+0]);
            tg[j+1] = fmaf(yh, wv.y, tg[j+1]);
            tg[j+2] = fmaf(yh, wv.z, tg[j+2]);
            tg[j+3] = fmaf(yh, wv.w, tg[j+3]);
        }
    }
    #pragma unroll
    for (int j = 0; j < HG; j++) tg[j] = fmaxf(tg[j], 0.f);

    float o2[DPE];
    #pragma unroll
    for (int d = 0; d < DPE; d++) o2[d] = bg2s[d];
    #pragma unroll
    for (int j = 0; j < HG; j++) {
        float tj = tg[j];
        #pragma unroll
        for (int d = 0; d < DPE; d += 4) {
            float4 wv = *(const float4*)&Wg2s[j*DPE + d];
            o2[d+0] = fmaf(tj, wv.x, o2[d+0]);
            o2[d+1] = fmaf(tj, wv.y, o2[d+1]);
            o2[d+2] = fmaf(tj, wv.z, o2[d+2]);
            o2[d+3] = fmaf(tj, wv.w, o2[d+3]);
        }
    }

    float* op = out + (size_t)(base + t)*DPE;
    *(float4*)&op[0]  = make_float4(o2[0],  o2[1],  o2[2],  o2[3]);
    *(float4*)&op[4]  = make_float4(o2[4],  o2[5],  o2[6],  o2[7]);
    *(float4*)&op[8]  = make_float4(o2[8],  o2[9],  o2[10], o2[11]);
    *(float4*)&op[12] = make_float4(o2[12], o2[13], o2[14], o2[15]);
}

// ---------------------------------------------------------------------------
extern "C" void kernel_launch(void* const* d_in, const int* in_sizes, int n_in,
                              void* d_out, int out_size)
{
    const float* Lambda = (const float*)d_in[0];
    const float* V      = (const float*)d_in[1];
    const float* pW1    = (const float*)d_in[2];
    const float* pb1    = (const float*)d_in[3];
    const float* pW2    = (const float*)d_in[4];
    const float* pb2    = (const float*)d_in[5];
    const float* Wp1    = (const float*)d_in[6];
    const float* bp1    = (const float*)d_in[7];
    const float* Wg1    = (const float*)d_in[8];
    const float* bg1    = (const float*)d_in[9];
    const float* Wg2    = (const float*)d_in[10];
    const float* bg2    = (const float*)d_in[11];
    const float* eps    = (const float*)d_in[12];
    const int*   edge_index = (const int*)d_in[13];
    const int*   batch  = (const int*)d_in[14];
    float* out = (float*)d_out;

    const int smemB = (3*NN*VPAD + 64) * (int)sizeof(float);   // 61696 B
    cudaFuncSetAttribute(kernelB, cudaFuncAttributeMaxDynamicSharedMemorySize, smemB);

    kernelB<<<NB, 256, smemB>>>(V, Lambda, pW1, pb1, pW2, pb2, Wp1, bp1, batch);
    kernelC<<<NB, 256>>>(Wg1, bg1, Wg2, bg2, eps, edge_index, out);
}